// round 15
// baseline (speedup 1.0000x reference)
#include <cuda_runtime.h>
#include <cuda_bf16.h>
#include <stdint.h>
#include <math.h>

#define BB 4
#define TT 2048
#define CC 1024
#define MT (BB*TT)   // 8192

typedef __nv_bfloat16 bf16;

// ---------------- Scratch ----------------
static __device__ bf16 g_Xh[MT*CC], g_Xl[MT*CC];
static __device__ bf16 g_Wqh[CC*CC], g_Wql[CC*CC];
static __device__ bf16 g_Wkh[CC*CC], g_Wkl[CC*CC];
static __device__ bf16 g_Wvh[CC*CC], g_Wvl[CC*CC];
static __device__ bf16 g_Woh[CC*CC], g_Wol[CC*CC];
static __device__ bf16 g_Qh[MT*CC], g_Ql[MT*CC];
static __device__ bf16 g_Kh[MT*CC], g_Kl[MT*CC];
static __device__ bf16 g_Vth[MT*CC], g_Vtl[MT*CC];   // [b][c][t]
static __device__ float g_S[(size_t)BB*TT*TT];
static __device__ bf16 g_Ph[(size_t)BB*TT*TT], g_Pl[(size_t)BB*TT*TT];
static __device__ bf16 g_Oh[MT*CC], g_Ol[MT*CC];

// ---------------- helpers ----------------
__device__ __forceinline__ uint32_t smem_u32(const void* p) {
    uint32_t a;
    asm("{ .reg .u64 t; cvta.to.shared.u64 t, %1; cvt.u32.u64 %0, t; }" : "=r"(a) : "l"(p));
    return a;
}
#define CP16(s, g) asm volatile("cp.async.cg.shared.global [%0], [%1], 16;" :: "r"(s), "l"(g) : "memory")
#define CPCOMMIT()  asm volatile("cp.async.commit_group;" ::: "memory")
#define CPWAIT1()   asm volatile("cp.async.wait_group 1;" ::: "memory")
#define LDSM4(r0,r1,r2,r3,a) \
    asm volatile("ldmatrix.sync.aligned.m8n8.x4.shared.b16 {%0,%1,%2,%3}, [%4];" \
                 : "=r"(r0),"=r"(r1),"=r"(r2),"=r"(r3) : "r"(a))

__device__ __forceinline__ void mma16816(float* c, const uint32_t* a, uint32_t b0, uint32_t b1) {
    asm volatile(
        "mma.sync.aligned.m16n8k16.row.col.f32.bf16.bf16.f32 "
        "{%0,%1,%2,%3}, {%4,%5,%6,%7}, {%8,%9}, {%0,%1,%2,%3};"
        : "+f"(c[0]), "+f"(c[1]), "+f"(c[2]), "+f"(c[3])
        : "r"(a[0]), "r"(a[1]), "r"(a[2]), "r"(a[3]), "r"(b0), "r"(b1));
}

__device__ __forceinline__ void split2(float x, bf16& h, bf16& l) {
    h = __float2bfloat16(x);
    l = __float2bfloat16(x - __bfloat162float(h));
}

// swizzled byte offset inside a (rows x 32) bf16 tile (64B rows) — R4-proven
__device__ __forceinline__ uint32_t swz(int row, int kbyte) {
    return (uint32_t)(row * 64 + (kbyte ^ ((row & 6) << 3)));
}

// ---------------- GEMM config: 128x128 CTA, BK=32, 3-stage, 2 CTA/SM ----------------
static constexpr int BK = 32;
static constexpr int TILE_T = 128 * BK * 2;          // 8 KB per term (A and B both 128 rows)
static constexpr int OFF_AH = 0, OFF_AL = TILE_T, OFF_BH = 2*TILE_T, OFF_BL = 3*TILE_T;
static constexpr int STAGE_B = 4 * TILE_T;           // 32 KB
static constexpr int STAGES = 3;
static constexpr int SMEM_DYN = STAGES * STAGE_B;    // 96 KB

// ---------------- GEMM: D = A @ B^T, bf16 hi/lo 3-term ----------------
// CTA 128x128xBK32, 8 warps (warp 32x64, 4m x 2n), 3-stage cp.async (R4 skeleton).
// MODE 0: epi fp32*alpha
// MODE 3: causal tile-skip (bx > by) + epi fp32*alpha
// MODE 4: k-limit, by reversed (heavy-first) + epi bf16 hi/lo
// MODE 5: fused QKV: bx>>3 selects {Q,K,V}; V epilogue transposed per-batch
template <int MODE>
__global__ __launch_bounds__(256, 2)
void gemm_mma(const bf16* __restrict__ Ah, const bf16* __restrict__ Al,
              const bf16* __restrict__ Bh, const bf16* __restrict__ Bl,
              float* __restrict__ Cf, bf16* __restrict__ Ch, bf16* __restrict__ Cl,
              const bf16* __restrict__ Bkh, const bf16* __restrict__ Bkl,
              const bf16* __restrict__ Bvh, const bf16* __restrict__ Bvl,
              bf16* __restrict__ Ckh, bf16* __restrict__ Ckl,
              bf16* __restrict__ Cvh, bf16* __restrict__ Cvl,
              int lda, int ldb, int kmax, int Nc,
              size_t sA, size_t sB, size_t sC, float alpha)
{
    const int bx = blockIdx.x, bz = blockIdx.z;
    int by = blockIdx.y;
    if (MODE == 4) by = (int)gridDim.y - 1 - by;     // heavy-first (LPT)
    if (MODE == 3 && bx > by) return;                // 128-granular causal skip
    const int m0 = by * 128;
    int n0 = bx * 128;
    if (MODE == 4) kmax = (by + 1) * 128;

    const bf16* pAh = Ah + bz * sA;
    const bf16* pAl = Al + bz * sA;
    const bf16* pBh = Bh + bz * sB;
    const bf16* pBl = Bl + bz * sB;
    bf16* outCh = Ch;
    bf16* outCl = Cl;
    int which = 0;
    if (MODE == 5) {
        which = bx >> 3;
        n0 = (bx & 7) * 128;
        if (which == 1) { pBh = Bkh; pBl = Bkl; outCh = Ckh; outCl = Ckl; }
        else if (which == 2) { pBh = Bvh; pBl = Bvl; outCh = Cvh; outCl = Cvl; }
    }

    extern __shared__ char dsm[];
    const uint32_t sbase = smem_u32(dsm);

    const int tid = threadIdx.x;
    const int wid = tid >> 5, lane = tid & 31;
    const int wm = wid & 3, wn = wid >> 2;       // warp tile: rows wm*32, cols wn*64

    // loader mapping: per term, 128 rows x 64B -> 512 chunks of 16B, 2/thread
    const int r0c = tid >> 2, k0c = (tid & 3) << 4;  // row 0..63, kbyte 0..48
    const uint32_t so0 = swz(r0c, k0c);
    const uint32_t so1 = swz(r0c + 64, k0c);

    // ldmatrix offsets (2 ks-steps of 16 K-elems)
    const int lr = lane & 15, lc16 = (lane >> 4) << 4;
    uint32_t aoff[2][2], boff[4][2];
    #pragma unroll
    for (int mi = 0; mi < 2; mi++) {
        int row = wm * 32 + mi * 16 + lr;
        #pragma unroll
        for (int ks = 0; ks < 2; ks++) aoff[mi][ks] = swz(row, ks * 32 + lc16);
    }
    #pragma unroll
    for (int nb = 0; nb < 4; nb++) {
        int row = wn * 64 + nb * 16 + lr;
        #pragma unroll
        for (int ks = 0; ks < 2; ks++) boff[nb][ks] = swz(row, ks * 32 + lc16);
    }

    float acc[2][8][4];
    #pragma unroll
    for (int mi = 0; mi < 2; mi++)
        #pragma unroll
        for (int nf = 0; nf < 8; nf++)
            #pragma unroll
            for (int q = 0; q < 4; q++) acc[mi][nf][q] = 0.0f;

    const int nit = kmax / BK;

    auto prefetch = [&](int it, int stage) {
        const int k0 = it * BK + (k0c >> 1);
        const uint32_t sb = sbase + stage * STAGE_B;
        CP16(sb + OFF_AH + so0, pAh + (size_t)(m0 + r0c) * lda + k0);
        CP16(sb + OFF_AH + so1, pAh + (size_t)(m0 + r0c + 64) * lda + k0);
        CP16(sb + OFF_AL + so0, pAl + (size_t)(m0 + r0c) * lda + k0);
        CP16(sb + OFF_AL + so1, pAl + (size_t)(m0 + r0c + 64) * lda + k0);
        CP16(sb + OFF_BH + so0, pBh + (size_t)(n0 + r0c) * ldb + k0);
        CP16(sb + OFF_BH + so1, pBh + (size_t)(n0 + r0c + 64) * ldb + k0);
        CP16(sb + OFF_BL + so0, pBl + (size_t)(n0 + r0c) * ldb + k0);
        CP16(sb + OFF_BL + so1, pBl + (size_t)(n0 + r0c + 64) * ldb + k0);
    };

    prefetch(0, 0); CPCOMMIT();
    if (nit > 1) prefetch(1, 1);
    CPCOMMIT();

    for (int it = 0; it < nit; it++) {
        CPWAIT1();
        __syncthreads();
        if (it + 2 < nit) prefetch(it + 2, (it + 2) % STAGES);
        CPCOMMIT();

        const uint32_t sb = sbase + (it % STAGES) * STAGE_B;
        #pragma unroll
        for (int ks = 0; ks < 2; ks++) {
            uint32_t Afr[2][4], Bt[4][4];
            #pragma unroll
            for (int mi = 0; mi < 2; mi++)
                LDSM4(Afr[mi][0], Afr[mi][1], Afr[mi][2], Afr[mi][3], sb + OFF_AH + aoff[mi][ks]);
            #pragma unroll
            for (int nb = 0; nb < 4; nb++)
                LDSM4(Bt[nb][0], Bt[nb][1], Bt[nb][2], Bt[nb][3], sb + OFF_BH + boff[nb][ks]);
            // hi*hi
            #pragma unroll
            for (int mi = 0; mi < 2; mi++)
                #pragma unroll
                for (int nf = 0; nf < 8; nf++)
                    mma16816(acc[mi][nf], Afr[mi], Bt[nf >> 1][nf & 1], Bt[nf >> 1][(nf & 1) + 2]);
            // lo*hi
            {
                uint32_t Alf[2][4];
                #pragma unroll
                for (int mi = 0; mi < 2; mi++)
                    LDSM4(Alf[mi][0], Alf[mi][1], Alf[mi][2], Alf[mi][3], sb + OFF_AL + aoff[mi][ks]);
                #pragma unroll
                for (int mi = 0; mi < 2; mi++)
                    #pragma unroll
                    for (int nf = 0; nf < 8; nf++)
                        mma16816(acc[mi][nf], Alf[mi], Bt[nf >> 1][nf & 1], Bt[nf >> 1][(nf & 1) + 2]);
            }
            // hi*lo (overwrite Bt with B-lo; Afr reused)
            #pragma unroll
            for (int nb = 0; nb < 4; nb++)
                LDSM4(Bt[nb][0], Bt[nb][1], Bt[nb][2], Bt[nb][3], sb + OFF_BL + boff[nb][ks]);
            #pragma unroll
            for (int mi = 0; mi < 2; mi++)
                #pragma unroll
                for (int nf = 0; nf < 8; nf++)
                    mma16816(acc[mi][nf], Afr[mi], Bt[nf >> 1][nf & 1], Bt[nf >> 1][(nf & 1) + 2]);
        }
    }

    // ---------------- epilogue ----------------
    const int quad = lane >> 2, tq = lane & 3;
    #pragma unroll
    for (int mi = 0; mi < 2; mi++) {
        #pragma unroll
        for (int h = 0; h < 2; h++) {
            const int r = m0 + wm * 32 + mi * 16 + quad + h * 8;
            if (MODE == 0 || MODE == 3) {
                float* crow = Cf + bz * sC + (size_t)r * Nc + n0 + wn * 64 + tq * 2;
                #pragma unroll
                for (int nf = 0; nf < 8; nf++) {
                    float2 v;
                    v.x = acc[mi][nf][h * 2 + 0] * alpha;
                    v.y = acc[mi][nf][h * 2 + 1] * alpha;
                    *(float2*)(crow + nf * 8) = v;
                }
            } else if (MODE == 4 || (MODE == 5 && which < 2)) {
                bf16* hrow = outCh + bz * sC + (size_t)r * Nc + n0 + wn * 64 + tq * 2;
                bf16* lrow = outCl + bz * sC + (size_t)r * Nc + n0 + wn * 64 + tq * 2;
                #pragma unroll
                for (int nf = 0; nf < 8; nf++) {
                    bf16 h0, l0, h1, l1;
                    split2(acc[mi][nf][h * 2 + 0], h0, l0);
                    split2(acc[mi][nf][h * 2 + 1], h1, l1);
                    __nv_bfloat162 hp; hp.x = h0; hp.y = h1;
                    __nv_bfloat162 lp; lp.x = l0; lp.y = l1;
                    *(__nv_bfloat162*)(hrow + nf * 8) = hp;
                    *(__nv_bfloat162*)(lrow + nf * 8) = lp;
                }
            } else {  // MODE 5, V: transposed Vt[b][c][t]
                const int b = r >> 11, t = r & (TT - 1);
                const size_t base = (size_t)b * CC * TT + t;
                #pragma unroll
                for (int nf = 0; nf < 8; nf++) {
                    const int c = n0 + wn * 64 + nf * 8 + tq * 2;
                    bf16 h0, l0, h1, l1;
                    split2(acc[mi][nf][h * 2 + 0], h0, l0);
                    split2(acc[mi][nf][h * 2 + 1], h1, l1);
                    outCh[base + (size_t)c * TT] = h0;
                    outCl[base + (size_t)c * TT] = l0;
                    outCh[base + (size_t)(c + 1) * TT] = h1;
                    outCl[base + (size_t)(c + 1) * TT] = l1;
                }
            }
        }
    }
}

// ---------------- fp32 -> bf16 hi/lo split ----------------
__global__ __launch_bounds__(256)
void split_f32(const float* __restrict__ x, bf16* __restrict__ h, bf16* __restrict__ l, int n)
{
    int i = (blockIdx.x * 256 + threadIdx.x) * 4;
    if (i >= n) return;
    float4 v = *(const float4*)(x + i);
    __align__(8) bf16 hh[4], ll[4];
    split2(v.x, hh[0], ll[0]); split2(v.y, hh[1], ll[1]);
    split2(v.z, hh[2], ll[2]); split2(v.w, hh[3], ll[3]);
    *(uint2*)(h + i) = *(uint2*)hh;
    *(uint2*)(l + i) = *(uint2*)ll;
}

// 4 weight matrices: W[k][n] -> Wt hi/lo [n][k], z selects matrix
__global__ __launch_bounds__(256)
void wsplitT4(const float* __restrict__ w0, const float* __restrict__ w1,
              const float* __restrict__ w2, const float* __restrict__ w3,
              bf16* __restrict__ h0, bf16* __restrict__ h1,
              bf16* __restrict__ h2, bf16* __restrict__ h3,
              bf16* __restrict__ l0, bf16* __restrict__ l1,
              bf16* __restrict__ l2, bf16* __restrict__ l3)
{
    const int z = blockIdx.z;
    const float* W = (z == 0) ? w0 : (z == 1) ? w1 : (z == 2) ? w2 : w3;
    bf16* Th = (z == 0) ? h0 : (z == 1) ? h1 : (z == 2) ? h2 : h3;
    bf16* Tl = (z == 0) ? l0 : (z == 1) ? l1 : (z == 2) ? l2 : l3;

    __shared__ float t[32][33];
    const int n0 = blockIdx.x * 32, k0 = blockIdx.y * 32;
    const int tx = threadIdx.x & 31, ty = threadIdx.x >> 5;
    #pragma unroll
    for (int i = 0; i < 4; i++)
        t[ty + 8*i][tx] = W[(size_t)(k0 + ty + 8*i) * CC + n0 + tx];
    __syncthreads();
    #pragma unroll
    for (int i = 0; i < 4; i++) {
        float v = t[tx][ty + 8*i];
        bf16 h, l;
        split2(v, h, l);
        Th[(size_t)(n0 + ty + 8*i) * CC + k0 + tx] = h;
        Tl[(size_t)(n0 + ty + 8*i) * CC + k0 + tx] = l;
    }
}

// ---------------- causal softmax: register-resident single pass ----------------
__global__ __launch_bounds__(256)
void softmax_causal(const float* __restrict__ S, bf16* __restrict__ Ph, bf16* __restrict__ Pl)
{
    const int r = blockIdx.x;
    const int t = r & (TT - 1);
    const float* row = S + (size_t)r * TT;
    bf16* ph = Ph + (size_t)r * TT;
    bf16* pl = Pl + (size_t)r * TT;
    const int len = t + 1;
    const int zmax = ((t >> 7) + 1) << 7;

    const int tid = threadIdx.x, lane = tid & 31, wid = tid >> 5;
    __shared__ float red[32];

    float v[8];
    float m = -3.0e38f;
    #pragma unroll
    for (int i = 0; i < 8; i++) {
        int s = tid + i * 256;
        v[i] = (s < len) ? row[s] : -3.0e38f;
        m = fmaxf(m, v[i]);
    }
    #pragma unroll
    for (int o = 16; o > 0; o >>= 1) m = fmaxf(m, __shfl_xor_sync(0xffffffffu, m, o));
    if (lane == 0) red[wid] = m;
    __syncthreads();
    if (tid < 32) {
        float x = (tid < 8) ? red[tid] : -3.0e38f;
        #pragma unroll
        for (int o = 4; o > 0; o >>= 1) x = fmaxf(x, __shfl_xor_sync(0xffffffffu, x, o));
        if (tid == 0) red[0] = x;
    }
    __syncthreads();
    m = red[0];
    __syncthreads();

    float sum = 0.0f;
    #pragma unroll
    for (int i = 0; i < 8; i++) {
        int s = tid + i * 256;
        if (s < len) { v[i] = expf(v[i] - m); sum += v[i]; }
    }
    #pragma unroll
    for (int o = 16; o > 0; o >>= 1) sum += __shfl_xor_sync(0xffffffffu, sum, o);
    if (lane == 0) red[wid] = sum;
    __syncthreads();
    if (tid < 32) {
        float x = (tid < 8) ? red[tid] : 0.0f;
        #pragma unroll
        for (int o = 4; o > 0; o >>= 1) x += __shfl_xor_sync(0xffffffffu, x, o);
        if (tid == 0) red[0] = x;
    }
    __syncthreads();
    const float inv = 1.0f / red[0];

    const bf16 z = __float2bfloat16(0.0f);
    #pragma unroll
    for (int i = 0; i < 8; i++) {
        int s = tid + i * 256;
        if (s < len) {
            bf16 h, l;
            split2(v[i] * inv, h, l);
            ph[s] = h; pl[s] = l;
        } else if (s < zmax) {
            ph[s] = z; pl[s] = z;
        }
    }
}

// ---------------- launch ----------------
extern "C" void kernel_launch(void* const* d_in, const int* in_sizes, int n_in,
                              void* d_out, int out_size)
{
    const float* X  = (const float*)d_in[0];
    const float* Wq = (const float*)d_in[1];
    const float* Wk = (const float*)d_in[2];
    const float* Wv = (const float*)d_in[3];
    const float* Wo = (const float*)d_in[4];
    float* out = (float*)d_out;

    bf16 *Xh,*Xl,*Wqh,*Wql,*Wkh,*Wkl,*Wvh,*Wvl,*Woh,*Wol;
    bf16 *Qh,*Ql,*Kh,*Kl,*Vth,*Vtl,*Ph,*Pl,*Oh,*Ol;
    float* S;
    cudaGetSymbolAddress((void**)&Xh, g_Xh);   cudaGetSymbolAddress((void**)&Xl, g_Xl);
    cudaGetSymbolAddress((void**)&Wqh, g_Wqh); cudaGetSymbolAddress((void**)&Wql, g_Wql);
    cudaGetSymbolAddress((void**)&Wkh, g_Wkh); cudaGetSymbolAddress((void**)&Wkl, g_Wkl);
    cudaGetSymbolAddress((void**)&Wvh, g_Wvh); cudaGetSymbolAddress((void**)&Wvl, g_Wvl);
    cudaGetSymbolAddress((void**)&Woh, g_Woh); cudaGetSymbolAddress((void**)&Wol, g_Wol);
    cudaGetSymbolAddress((void**)&Qh, g_Qh);   cudaGetSymbolAddress((void**)&Ql, g_Ql);
    cudaGetSymbolAddress((void**)&Kh, g_Kh);   cudaGetSymbolAddress((void**)&Kl, g_Kl);
    cudaGetSymbolAddress((void**)&Vth, g_Vth); cudaGetSymbolAddress((void**)&Vtl, g_Vtl);
    cudaGetSymbolAddress((void**)&Ph, g_Ph);   cudaGetSymbolAddress((void**)&Pl, g_Pl);
    cudaGetSymbolAddress((void**)&Oh, g_Oh);   cudaGetSymbolAddress((void**)&Ol, g_Ol);
    cudaGetSymbolAddress((void**)&S, g_S);

    cudaFuncSetAttribute(gemm_mma<0>, cudaFuncAttributeMaxDynamicSharedMemorySize, SMEM_DYN);
    cudaFuncSetAttribute(gemm_mma<3>, cudaFuncAttributeMaxDynamicSharedMemorySize, SMEM_DYN);
    cudaFuncSetAttribute(gemm_mma<4>, cudaFuncAttributeMaxDynamicSharedMemorySize, SMEM_DYN);
    cudaFuncSetAttribute(gemm_mma<5>, cudaFuncAttributeMaxDynamicSharedMemorySize, SMEM_DYN);

    // 1) input split
    split_f32<<<MT*CC/1024, 256>>>(X, Xh, Xl, MT*CC);
    // 2) weight transposes/splits
    wsplitT4<<<dim3(32,32,4), 256>>>(Wq, Wk, Wv, Wo,
                                     Wqh, Wkh, Wvh, Woh,
                                     Wql, Wkl, Wvl, Wol);

    // 3) fused QKV (bx: 0-7 Q, 8-15 K, 16-23 V-transposed)
    gemm_mma<5><<<dim3(24,64,1), 256, SMEM_DYN>>>(Xh, Xl, Wqh, Wql, nullptr, Qh, Ql,
                                                  Wkh, Wkl, Wvh, Wvl, Kh, Kl, Vth, Vtl,
                                                  CC, CC, CC, CC, 0, 0, 0, 1.0f);

    // 4) scores (causal tile-skip, 128x128 tiles)
    gemm_mma<3><<<dim3(16,16,4), 256, SMEM_DYN>>>(Qh, Ql, Kh, Kl, S, nullptr, nullptr,
                                                  nullptr,nullptr,nullptr,nullptr,
                                                  nullptr,nullptr,nullptr,nullptr,
                                                  CC, CC, CC, TT,
                                                  (size_t)TT*CC, (size_t)TT*CC, (size_t)TT*TT,
                                                  1.0f/32.0f);

    // 5) softmax -> P hi/lo
    softmax_causal<<<BB*TT, 256>>>(S, Ph, Pl);

    // 6) O = P @ Vt^T (k-limited, heavy-first)
    gemm_mma<4><<<dim3(8,16,4), 256, SMEM_DYN>>>(Ph, Pl, Vth, Vtl, nullptr, Oh, Ol,
                                                 nullptr,nullptr,nullptr,nullptr,
                                                 nullptr,nullptr,nullptr,nullptr,
                                                 TT, TT, TT, CC,
                                                 (size_t)TT*TT, (size_t)CC*TT, (size_t)TT*CC,
                                                 1.0f);

    // 7) out = O @ Wo^T
    gemm_mma<0><<<dim3(8,64,1), 256, SMEM_DYN>>>(Oh, Ol, Woh, Wol, out, nullptr, nullptr,
                                                 nullptr,nullptr,nullptr,nullptr,
                                                 nullptr,nullptr,nullptr,nullptr,
                                                 CC, CC, CC, CC, 0, 0, 0, 1.0f);
}

// round 16
// speedup vs baseline: 1.5195x; 1.5195x over previous
#include <cuda_runtime.h>
#include <cuda_fp16.h>
#include <stdint.h>
#include <math.h>

#define BB 4
#define TT 2048
#define CC 1024
#define MT (BB*TT)   // 8192

typedef __half fp16;

// ---------------- Scratch ----------------
static __device__ fp16 g_Xh[MT*CC], g_Xl[MT*CC];
static __device__ fp16 g_Wqh[CC*CC], g_Wkh[CC*CC], g_Wvh[CC*CC], g_Woh[CC*CC];
static __device__ fp16 g_Qh[MT*CC], g_Ql[MT*CC];
static __device__ fp16 g_Kh[MT*CC], g_Kl[MT*CC];     // Kl written, unused (epilogue reuse)
static __device__ fp16 g_Vth[MT*CC];                 // [b][c][t] transposed V (hi only)
static __device__ float g_S[(size_t)BB*TT*TT];
static __device__ fp16 g_Ph[(size_t)BB*TT*TT], g_Pl[(size_t)BB*TT*TT];
static __device__ fp16 g_Oh[MT*CC], g_Ol[MT*CC];

// ---------------- helpers ----------------
__device__ __forceinline__ uint32_t smem_u32(const void* p) {
    uint32_t a;
    asm("{ .reg .u64 t; cvta.to.shared.u64 t, %1; cvt.u32.u64 %0, t; }" : "=r"(a) : "l"(p));
    return a;
}
#define CP16(s, g) asm volatile("cp.async.cg.shared.global [%0], [%1], 16;" :: "r"(s), "l"(g) : "memory")
#define CPCOMMIT()  asm volatile("cp.async.commit_group;" ::: "memory")
#define CPWAIT1()   asm volatile("cp.async.wait_group 1;" ::: "memory")
#define CPWAIT0()   asm volatile("cp.async.wait_group 0;" ::: "memory")
#define LDSM4(r0,r1,r2,r3,a) \
    asm volatile("ldmatrix.sync.aligned.m8n8.x4.shared.b16 {%0,%1,%2,%3}, [%4];" \
                 : "=r"(r0),"=r"(r1),"=r"(r2),"=r"(r3) : "r"(a))

__device__ __forceinline__ void mma16816(float* c, const uint32_t* a, uint32_t b0, uint32_t b1) {
    asm volatile(
        "mma.sync.aligned.m16n8k16.row.col.f32.f16.f16.f32 "
        "{%0,%1,%2,%3}, {%4,%5,%6,%7}, {%8,%9}, {%0,%1,%2,%3};"
        : "+f"(c[0]), "+f"(c[1]), "+f"(c[2]), "+f"(c[3])
        : "r"(a[0]), "r"(a[1]), "r"(a[2]), "r"(a[3]), "r"(b0), "r"(b1));
}

__device__ __forceinline__ void split2h(float x, fp16& h, fp16& l) {
    h = __float2half_rn(x);
    l = __float2half_rn(x - __half2float(h));
}

// SW128 swizzled byte offset inside a (rows x 64) fp16 tile (128B rows)
__device__ __forceinline__ uint32_t swz128(int row, int kbyte) {
    return (uint32_t)(row * 128 + (kbyte ^ ((row & 7) << 4)));
}

// ---------------- GEMM config: 128x64 tile, BK=64, 2-stage (R10 skeleton) ----------------
static constexpr int BK = 64;
static constexpr int TILE_A = 128 * BK * 2;          // 16 KB per A term
static constexpr int TILE_Bb = 64 * BK * 2;          // 8 KB (B hi only)
static constexpr int OFF_AH = 0, OFF_AL = TILE_A, OFF_BH = 2*TILE_A;
static constexpr int STAGE_B = 2*TILE_A + TILE_Bb;   // 40 KB
static constexpr int SMEM_DYN = 2 * STAGE_B;         // 80 KB

// ---------------- GEMM: D = A @ B^T, fp16 2-term (Ah*Bh + Al*Bh) ----------------
// Tile 128x64xBK64, 8 warps (warp 32x32), 2-stage cp.async.
// MODE 0: epi fp32*alpha
// MODE 3: causal tile-skip (bx*64 > by*128+127) + epi fp32*alpha
// MODE 4: k-limit, by reversed (heavy-first) + epi fp16 hi/lo
// MODE 5: fused QKV: bx>>4 selects {Q,K,V}; V epilogue transposed h-only per-batch
template <int MODE>
__global__ __launch_bounds__(256, 2)
void gemm_mma(const fp16* __restrict__ Ah, const fp16* __restrict__ Al,
              const fp16* __restrict__ Bh,
              float* __restrict__ Cf, fp16* __restrict__ Ch, fp16* __restrict__ Cl,
              const fp16* __restrict__ Bkh, const fp16* __restrict__ Bvh,
              fp16* __restrict__ Ckh, fp16* __restrict__ Ckl,
              fp16* __restrict__ Cvh,
              int lda, int ldb, int kmax, int Nc,
              size_t sA, size_t sB, size_t sC, float alpha)
{
    const int bx = blockIdx.x, bz = blockIdx.z;
    int by = blockIdx.y;
    if (MODE == 4) by = (int)gridDim.y - 1 - by;     // heavy-first (LPT)
    if (MODE == 3 && bx * 64 > by * 128 + 127) return;
    const int m0 = by * 128;
    int n0 = bx * 64;
    if (MODE == 4) kmax = (by + 1) * 128;

    const fp16* pAh = Ah + bz * sA;
    const fp16* pAl = Al + bz * sA;
    const fp16* pBh = Bh + bz * sB;
    fp16* outCh = Ch;
    fp16* outCl = Cl;
    int which = 0;
    if (MODE == 5) {
        which = bx >> 4;
        n0 = (bx & 15) * 64;
        if (which == 1) { pBh = Bkh; outCh = Ckh; outCl = Ckl; }
        else if (which == 2) { pBh = Bvh; outCh = Cvh; }
    }

    extern __shared__ char dsm[];
    const uint32_t sbase = smem_u32(dsm);

    const int tid = threadIdx.x;
    const int wid = tid >> 5, lane = tid & 31;
    const int wm = wid & 3, wn = wid >> 2;       // warp tile: rows wm*32, cols wn*32

    // loader mapping: 16B chunks; A = 4 chunks/term, B = 2 chunks
    const int r0 = tid >> 3;                      // 0..31
    const int c0 = (tid & 7) << 4;                // byte col 0..112
    uint32_t so[4];
    #pragma unroll
    for (int i = 0; i < 4; i++) so[i] = swz128(r0 + 32 * i, c0);

    // ldmatrix offsets (4 ks-steps of 16 K-elems each)
    const int lr = lane & 15, lc16 = (lane >> 4) << 4;
    uint32_t aoff[2][4], boff[2][4];
    #pragma unroll
    for (int mi = 0; mi < 2; mi++) {
        int row = wm * 32 + mi * 16 + lr;
        #pragma unroll
        for (int ks = 0; ks < 4; ks++) aoff[mi][ks] = swz128(row, ks * 32 + lc16);
    }
    #pragma unroll
    for (int nb = 0; nb < 2; nb++) {
        int row = wn * 32 + nb * 16 + lr;
        #pragma unroll
        for (int ks = 0; ks < 4; ks++) boff[nb][ks] = swz128(row, ks * 32 + lc16);
    }

    float acc[2][4][4];
    #pragma unroll
    for (int mi = 0; mi < 2; mi++)
        #pragma unroll
        for (int nf = 0; nf < 4; nf++)
            #pragma unroll
            for (int q = 0; q < 4; q++) acc[mi][nf][q] = 0.0f;

    const int nit = kmax / BK;

    auto prefetch = [&](int it) {
        const int k0 = it * BK + (c0 >> 1);
        const uint32_t sb = sbase + (it & 1) * STAGE_B;
        #pragma unroll
        for (int i = 0; i < 4; i++)
            CP16(sb + OFF_AH + so[i], pAh + (size_t)(m0 + r0 + 32 * i) * lda + k0);
        #pragma unroll
        for (int i = 0; i < 4; i++)
            CP16(sb + OFF_AL + so[i], pAl + (size_t)(m0 + r0 + 32 * i) * lda + k0);
        #pragma unroll
        for (int i = 0; i < 2; i++)
            CP16(sb + OFF_BH + so[i], pBh + (size_t)(n0 + r0 + 32 * i) * ldb + k0);
    };

    prefetch(0); CPCOMMIT();

    for (int it = 0; it < nit; it++) {
        if (it + 1 < nit) { prefetch(it + 1); CPCOMMIT(); CPWAIT1(); }
        else              { CPWAIT0(); }
        __syncthreads();                          // stage it data ready for all warps

        const uint32_t sb = sbase + (it & 1) * STAGE_B;
        #pragma unroll
        for (int ks = 0; ks < 4; ks++) {
            uint32_t Afr[2][4], Bt[2][4];
            #pragma unroll
            for (int mi = 0; mi < 2; mi++)
                LDSM4(Afr[mi][0], Afr[mi][1], Afr[mi][2], Afr[mi][3], sb + OFF_AH + aoff[mi][ks]);
            #pragma unroll
            for (int nb = 0; nb < 2; nb++)
                LDSM4(Bt[nb][0], Bt[nb][1], Bt[nb][2], Bt[nb][3], sb + OFF_BH + boff[nb][ks]);
            // hi*hi
            #pragma unroll
            for (int mi = 0; mi < 2; mi++)
                #pragma unroll
                for (int nf = 0; nf < 4; nf++)
                    mma16816(acc[mi][nf], Afr[mi], Bt[nf >> 1][nf & 1], Bt[nf >> 1][(nf & 1) + 2]);
            // lo*hi (overwrite Afr with A-lo)
            #pragma unroll
            for (int mi = 0; mi < 2; mi++)
                LDSM4(Afr[mi][0], Afr[mi][1], Afr[mi][2], Afr[mi][3], sb + OFF_AL + aoff[mi][ks]);
            #pragma unroll
            for (int mi = 0; mi < 2; mi++)
                #pragma unroll
                for (int nf = 0; nf < 4; nf++)
                    mma16816(acc[mi][nf], Afr[mi], Bt[nf >> 1][nf & 1], Bt[nf >> 1][(nf & 1) + 2]);
        }
        __syncthreads();                          // all warps done before stage reuse
    }

    // ---------------- epilogue ----------------
    const int quad = lane >> 2, tq = lane & 3;
    #pragma unroll
    for (int mi = 0; mi < 2; mi++) {
        #pragma unroll
        for (int h = 0; h < 2; h++) {
            const int r = m0 + wm * 32 + mi * 16 + quad + h * 8;
            if (MODE == 0 || MODE == 3) {
                float* crow = Cf + bz * sC + (size_t)r * Nc + n0 + wn * 32 + tq * 2;
                #pragma unroll
                for (int nf = 0; nf < 4; nf++) {
                    float2 v;
                    v.x = acc[mi][nf][h * 2 + 0] * alpha;
                    v.y = acc[mi][nf][h * 2 + 1] * alpha;
                    *(float2*)(crow + nf * 8) = v;
                }
            } else if (MODE == 4 || (MODE == 5 && which < 2)) {
                fp16* hrow = outCh + bz * sC + (size_t)r * Nc + n0 + wn * 32 + tq * 2;
                fp16* lrow = outCl + bz * sC + (size_t)r * Nc + n0 + wn * 32 + tq * 2;
                #pragma unroll
                for (int nf = 0; nf < 4; nf++) {
                    fp16 h0, l0, h1, l1;
                    split2h(acc[mi][nf][h * 2 + 0], h0, l0);
                    split2h(acc[mi][nf][h * 2 + 1], h1, l1);
                    *(__half2*)(hrow + nf * 8) = __halves2half2(h0, h1);
                    *(__half2*)(lrow + nf * 8) = __halves2half2(l0, l1);
                }
            } else {  // MODE 5, V: transposed Vt[b][c][t], hi only
                const int b = r >> 11, t = r & (TT - 1);
                const size_t base = (size_t)b * CC * TT + t;
                #pragma unroll
                for (int nf = 0; nf < 4; nf++) {
                    const int c = n0 + wn * 32 + nf * 8 + tq * 2;
                    outCh[base + (size_t)c * TT]       = __float2half_rn(acc[mi][nf][h * 2 + 0]);
                    outCh[base + (size_t)(c + 1) * TT] = __float2half_rn(acc[mi][nf][h * 2 + 1]);
                }
            }
        }
    }
}

// ---------------- fp32 -> fp16 hi/lo split ----------------
__global__ __launch_bounds__(256)
void split_f32(const float* __restrict__ x, fp16* __restrict__ h, fp16* __restrict__ l, int n)
{
    int i = (blockIdx.x * 256 + threadIdx.x) * 4;
    if (i >= n) return;
    float4 v = *(const float4*)(x + i);
    __align__(8) fp16 hh[4], ll[4];
    split2h(v.x, hh[0], ll[0]); split2h(v.y, hh[1], ll[1]);
    split2h(v.z, hh[2], ll[2]); split2h(v.w, hh[3], ll[3]);
    *(uint2*)(h + i) = *(uint2*)hh;
    *(uint2*)(l + i) = *(uint2*)ll;
}

// 4 weight matrices: W[k][n] -> Wt hi-only [n][k], z selects matrix
__global__ __launch_bounds__(256)
void wsplitT4(const float* __restrict__ w0, const float* __restrict__ w1,
              const float* __restrict__ w2, const float* __restrict__ w3,
              fp16* __restrict__ h0, fp16* __restrict__ h1,
              fp16* __restrict__ h2, fp16* __restrict__ h3)
{
    const int z = blockIdx.z;
    const float* W = (z == 0) ? w0 : (z == 1) ? w1 : (z == 2) ? w2 : w3;
    fp16* Th = (z == 0) ? h0 : (z == 1) ? h1 : (z == 2) ? h2 : h3;

    __shared__ float t[32][33];
    const int n0 = blockIdx.x * 32, k0 = blockIdx.y * 32;
    const int tx = threadIdx.x & 31, ty = threadIdx.x >> 5;
    #pragma unroll
    for (int i = 0; i < 4; i++)
        t[ty + 8*i][tx] = W[(size_t)(k0 + ty + 8*i) * CC + n0 + tx];
    __syncthreads();
    #pragma unroll
    for (int i = 0; i < 4; i++)
        Th[(size_t)(n0 + ty + 8*i) * CC + k0 + tx] = __float2half_rn(t[tx][ty + 8*i]);
}

// ---------------- causal softmax: fp32 row -> fp16 hi/lo probs ----------------
__global__ __launch_bounds__(256)
void softmax_causal(const float* __restrict__ S, fp16* __restrict__ Ph, fp16* __restrict__ Pl)
{
    const int r = blockIdx.x;
    const int t = r & (TT - 1);
    const float* row = S + (size_t)r * TT;
    fp16* ph = Ph + (size_t)r * TT;
    fp16* pl = Pl + (size_t)r * TT;
    const int len = t + 1;
    const int zmax = ((t >> 7) + 1) << 7;

    const int tid = threadIdx.x, lane = tid & 31, wid = tid >> 5;
    __shared__ float red[32];

    float v[8];
    float m = -3.0e38f;
    #pragma unroll
    for (int i = 0; i < 8; i++) {
        int s = tid + i * 256;
        v[i] = (s < len) ? row[s] : -3.0e38f;
        m = fmaxf(m, v[i]);
    }
    #pragma unroll
    for (int o = 16; o > 0; o >>= 1) m = fmaxf(m, __shfl_xor_sync(0xffffffffu, m, o));
    if (lane == 0) red[wid] = m;
    __syncthreads();
    if (tid < 32) {
        float x = (tid < 8) ? red[tid] : -3.0e38f;
        #pragma unroll
        for (int o = 4; o > 0; o >>= 1) x = fmaxf(x, __shfl_xor_sync(0xffffffffu, x, o));
        if (tid == 0) red[0] = x;
    }
    __syncthreads();
    m = red[0];
    __syncthreads();

    float sum = 0.0f;
    #pragma unroll
    for (int i = 0; i < 8; i++) {
        int s = tid + i * 256;
        if (s < len) { v[i] = expf(v[i] - m); sum += v[i]; }
    }
    #pragma unroll
    for (int o = 16; o > 0; o >>= 1) sum += __shfl_xor_sync(0xffffffffu, sum, o);
    if (lane == 0) red[wid] = sum;
    __syncthreads();
    if (tid < 32) {
        float x = (tid < 8) ? red[tid] : 0.0f;
        #pragma unroll
        for (int o = 4; o > 0; o >>= 1) x += __shfl_xor_sync(0xffffffffu, x, o);
        if (tid == 0) red[0] = x;
    }
    __syncthreads();
    const float inv = 1.0f / red[0];

    const fp16 z = __float2half_rn(0.0f);
    #pragma unroll
    for (int i = 0; i < 8; i++) {
        int s = tid + i * 256;
        if (s < len) {
            fp16 h, l;
            split2h(v[i] * inv, h, l);
            ph[s] = h; pl[s] = l;
        } else if (s < zmax) {
            ph[s] = z; pl[s] = z;
        }
    }
}

// ---------------- launch ----------------
extern "C" void kernel_launch(void* const* d_in, const int* in_sizes, int n_in,
                              void* d_out, int out_size)
{
    const float* X  = (const float*)d_in[0];
    const float* Wq = (const float*)d_in[1];
    const float* Wk = (const float*)d_in[2];
    const float* Wv = (const float*)d_in[3];
    const float* Wo = (const float*)d_in[4];
    float* out = (float*)d_out;

    fp16 *Xh,*Xl,*Wqh,*Wkh,*Wvh,*Woh;
    fp16 *Qh,*Ql,*Kh,*Kl,*Vth,*Ph,*Pl,*Oh,*Ol;
    float* S;
    cudaGetSymbolAddress((void**)&Xh, g_Xh);   cudaGetSymbolAddress((void**)&Xl, g_Xl);
    cudaGetSymbolAddress((void**)&Wqh, g_Wqh); cudaGetSymbolAddress((void**)&Wkh, g_Wkh);
    cudaGetSymbolAddress((void**)&Wvh, g_Wvh); cudaGetSymbolAddress((void**)&Woh, g_Woh);
    cudaGetSymbolAddress((void**)&Qh, g_Qh);   cudaGetSymbolAddress((void**)&Ql, g_Ql);
    cudaGetSymbolAddress((void**)&Kh, g_Kh);   cudaGetSymbolAddress((void**)&Kl, g_Kl);
    cudaGetSymbolAddress((void**)&Vth, g_Vth);
    cudaGetSymbolAddress((void**)&Ph, g_Ph);   cudaGetSymbolAddress((void**)&Pl, g_Pl);
    cudaGetSymbolAddress((void**)&Oh, g_Oh);   cudaGetSymbolAddress((void**)&Ol, g_Ol);
    cudaGetSymbolAddress((void**)&S, g_S);

    cudaFuncSetAttribute(gemm_mma<0>, cudaFuncAttributeMaxDynamicSharedMemorySize, SMEM_DYN);
    cudaFuncSetAttribute(gemm_mma<3>, cudaFuncAttributeMaxDynamicSharedMemorySize, SMEM_DYN);
    cudaFuncSetAttribute(gemm_mma<4>, cudaFuncAttributeMaxDynamicSharedMemorySize, SMEM_DYN);
    cudaFuncSetAttribute(gemm_mma<5>, cudaFuncAttributeMaxDynamicSharedMemorySize, SMEM_DYN);

    // 1) input split (fp16 hi/lo)
    split_f32<<<MT*CC/1024, 256>>>(X, Xh, Xl, MT*CC);
    // 2) weight transposes (fp16 hi only)
    wsplitT4<<<dim3(32,32,4), 256>>>(Wq, Wk, Wv, Wo, Wqh, Wkh, Wvh, Woh);

    // 3) fused QKV (bx: 0-15 Q, 16-31 K, 32-47 V-transposed)
    gemm_mma<5><<<dim3(48,64,1), 256, SMEM_DYN>>>(Xh, Xl, Wqh, nullptr, Qh, Ql,
                                                  Wkh, Wvh, Kh, Kl, Vth,
                                                  CC, CC, CC, CC, 0, 0, 0, 1.0f);

    // 4) scores (causal tile-skip): S = (Q @ K^T)/32
    gemm_mma<3><<<dim3(32,16,4), 256, SMEM_DYN>>>(Qh, Ql, Kh, S, nullptr, nullptr,
                                                  nullptr, nullptr, nullptr, nullptr, nullptr,
                                                  CC, CC, CC, TT,
                                                  (size_t)TT*CC, (size_t)TT*CC, (size_t)TT*TT,
                                                  1.0f/32.0f);

    // 5) softmax -> P hi/lo
    softmax_causal<<<BB*TT, 256>>>(S, Ph, Pl);

    // 6) O = P @ Vt^T (k-limited, heavy-first)
    gemm_mma<4><<<dim3(16,16,4), 256, SMEM_DYN>>>(Ph, Pl, Vth, nullptr, Oh, Ol,
                                                  nullptr, nullptr, nullptr, nullptr, nullptr,
                                                  TT, TT, TT, CC,
                                                  (size_t)TT*TT, (size_t)CC*TT, (size_t)TT*CC,
                                                  1.0f);

    // 7) out = O @ Wo^T
    gemm_mma<0><<<dim3(16,64,1), 256, SMEM_DYN>>>(Oh, Ol, Woh, out, nullptr, nullptr,
                                                  nullptr, nullptr, nullptr, nullptr, nullptr,
                                                  CC, CC, CC, CC, 0, 0, 0, 1.0f);
}

// round 17
// speedup vs baseline: 2.7980x; 1.8414x over previous
#include <cuda_runtime.h>
#include <cuda_fp16.h>
#include <stdint.h>
#include <math.h>

#define BB 4
#define TT 2048
#define CC 1024
#define MT (BB*TT)   // 8192

typedef __half fp16;

// ---------------- Scratch ----------------
static __device__ fp16 g_Xh[MT*CC];
static __device__ fp16 g_Wqh[CC*CC], g_Wkh[CC*CC], g_Wvh[CC*CC], g_Woh[CC*CC];
static __device__ fp16 g_Qh[MT*CC];
static __device__ fp16 g_Kh[MT*CC];
static __device__ fp16 g_Vth[MT*CC];                 // [b][c][t] transposed V
static __device__ float g_S[(size_t)BB*TT*TT];
static __device__ fp16 g_Ph[(size_t)BB*TT*TT];
static __device__ fp16 g_Oh[MT*CC];

// ---------------- helpers ----------------
__device__ __forceinline__ uint32_t smem_u32(const void* p) {
    uint32_t a;
    asm("{ .reg .u64 t; cvta.to.shared.u64 t, %1; cvt.u32.u64 %0, t; }" : "=r"(a) : "l"(p));
    return a;
}
#define CP16(s, g) asm volatile("cp.async.cg.shared.global [%0], [%1], 16;" :: "r"(s), "l"(g) : "memory")
#define CPCOMMIT()  asm volatile("cp.async.commit_group;" ::: "memory")
#define CPWAIT1()   asm volatile("cp.async.wait_group 1;" ::: "memory")
#define CPWAIT0()   asm volatile("cp.async.wait_group 0;" ::: "memory")
#define LDSM4(r0,r1,r2,r3,a) \
    asm volatile("ldmatrix.sync.aligned.m8n8.x4.shared.b16 {%0,%1,%2,%3}, [%4];" \
                 : "=r"(r0),"=r"(r1),"=r"(r2),"=r"(r3) : "r"(a))

__device__ __forceinline__ void mma16816(float* c, const uint32_t* a, uint32_t b0, uint32_t b1) {
    asm volatile(
        "mma.sync.aligned.m16n8k16.row.col.f32.f16.f16.f32 "
        "{%0,%1,%2,%3}, {%4,%5,%6,%7}, {%8,%9}, {%0,%1,%2,%3};"
        : "+f"(c[0]), "+f"(c[1]), "+f"(c[2]), "+f"(c[3])
        : "r"(a[0]), "r"(a[1]), "r"(a[2]), "r"(a[3]), "r"(b0), "r"(b1));
}

// SW128 swizzled byte offset inside a (rows x 64) fp16 tile (128B rows)
__device__ __forceinline__ uint32_t swz128(int row, int kbyte) {
    return (uint32_t)(row * 128 + (kbyte ^ ((row & 7) << 4)));
}

// ---------------- GEMM config: 128x128 CTA, BK=64, 2-stage, 1-term fp16 ----------------
static constexpr int BK = 64;
static constexpr int TILE_T = 128 * BK * 2;          // 16 KB (A and B each)
static constexpr int OFF_A = 0, OFF_B = TILE_T;
static constexpr int STAGE_B = 2 * TILE_T;           // 32 KB
static constexpr int SMEM_DYN = 2 * STAGE_B;         // 64 KB

// ---------------- GEMM: D = A @ B^T, plain fp16, fp32 accum ----------------
// CTA 128x128xBK64, 8 warps (warp 32x64, 4m x 2n), 2-stage cp.async.
// MODE 0: epi fp32*alpha
// MODE 3: causal tile-skip (bx > by) + epi fp32*alpha
// MODE 4: k-limit, by reversed (heavy-first) + epi fp16
// MODE 5: fused QKV: bx>>3 selects {Q,K,V}; V epilogue transposed per-batch
template <int MODE>
__global__ __launch_bounds__(256, 2)
void gemm_mma(const fp16* __restrict__ Ah, const fp16* __restrict__ Bh,
              float* __restrict__ Cf, fp16* __restrict__ Ch,
              const fp16* __restrict__ Bkh, const fp16* __restrict__ Bvh,
              fp16* __restrict__ Ckh, fp16* __restrict__ Cvh,
              int lda, int ldb, int kmax, int Nc,
              size_t sA, size_t sB, size_t sC, float alpha)
{
    const int bx = blockIdx.x, bz = blockIdx.z;
    int by = blockIdx.y;
    if (MODE == 4) by = (int)gridDim.y - 1 - by;     // heavy-first (LPT)
    if (MODE == 3 && bx > by) return;                // causal tile skip
    const int m0 = by * 128;
    int n0 = bx * 128;
    if (MODE == 4) kmax = (by + 1) * 128;

    const fp16* pAh = Ah + bz * sA;
    const fp16* pBh = Bh + bz * sB;
    fp16* outCh = Ch;
    int which = 0;
    if (MODE == 5) {
        which = bx >> 3;
        n0 = (bx & 7) * 128;
        if (which == 1) { pBh = Bkh; outCh = Ckh; }
        else if (which == 2) { pBh = Bvh; outCh = Cvh; }
    }

    extern __shared__ char dsm[];
    const uint32_t sbase = smem_u32(dsm);

    const int tid = threadIdx.x;
    const int wid = tid >> 5, lane = tid & 31;
    const int wm = wid & 3, wn = wid >> 2;       // warp tile: rows wm*32, cols wn*64

    // loader mapping: 16B chunks; A and B each 128 rows x 128B -> 4 chunks/thread each
    const int r0 = tid >> 3;                      // 0..31
    const int c0 = (tid & 7) << 4;                // byte col 0..112
    uint32_t so[4];
    #pragma unroll
    for (int i = 0; i < 4; i++) so[i] = swz128(r0 + 32 * i, c0);

    // ldmatrix BASE offsets (ks folded in via XOR: swz128(row, ks*32+lc16) = base ^ (ks<<5))
    const int lr = lane & 15, lc16 = (lane >> 4) << 4;
    uint32_t aoffb[2], boffb[4];
    #pragma unroll
    for (int mi = 0; mi < 2; mi++)
        aoffb[mi] = swz128(wm * 32 + mi * 16 + lr, lc16);
    #pragma unroll
    for (int nb = 0; nb < 4; nb++)
        boffb[nb] = swz128(wn * 64 + nb * 16 + lr, lc16);

    float acc[2][8][4];
    #pragma unroll
    for (int mi = 0; mi < 2; mi++)
        #pragma unroll
        for (int nf = 0; nf < 8; nf++)
            #pragma unroll
            for (int q = 0; q < 4; q++) acc[mi][nf][q] = 0.0f;

    const int nit = kmax / BK;

    auto prefetch = [&](int it) {
        const int k0 = it * BK + (c0 >> 1);
        const uint32_t sb = sbase + (it & 1) * STAGE_B;
        #pragma unroll
        for (int i = 0; i < 4; i++)
            CP16(sb + OFF_A + so[i], pAh + (size_t)(m0 + r0 + 32 * i) * lda + k0);
        #pragma unroll
        for (int i = 0; i < 4; i++)
            CP16(sb + OFF_B + so[i], pBh + (size_t)(n0 + r0 + 32 * i) * ldb + k0);
    };

    prefetch(0); CPCOMMIT();

    for (int it = 0; it < nit; it++) {
        if (it + 1 < nit) { prefetch(it + 1); CPCOMMIT(); CPWAIT1(); }
        else              { CPWAIT0(); }
        __syncthreads();                          // stage it data ready for all warps

        const uint32_t sb = sbase + (it & 1) * STAGE_B;
        #pragma unroll
        for (int ks = 0; ks < 4; ks++) {
            const uint32_t kx = (uint32_t)(ks << 5);
            uint32_t Af[2][4], Bt[4][4];
            #pragma unroll
            for (int mi = 0; mi < 2; mi++)
                LDSM4(Af[mi][0], Af[mi][1], Af[mi][2], Af[mi][3],
                      sb + OFF_A + (aoffb[mi] ^ kx));
            #pragma unroll
            for (int nb = 0; nb < 4; nb++)
                LDSM4(Bt[nb][0], Bt[nb][1], Bt[nb][2], Bt[nb][3],
                      sb + OFF_B + (boffb[nb] ^ kx));
            #pragma unroll
            for (int mi = 0; mi < 2; mi++)
                #pragma unroll
                for (int nf = 0; nf < 8; nf++)
                    mma16816(acc[mi][nf], Af[mi], Bt[nf >> 1][nf & 1], Bt[nf >> 1][(nf & 1) + 2]);
        }
        __syncthreads();                          // all warps done before stage reuse
    }

    // ---------------- epilogue ----------------
    const int quad = lane >> 2, tq = lane & 3;
    #pragma unroll
    for (int mi = 0; mi < 2; mi++) {
        #pragma unroll
        for (int h = 0; h < 2; h++) {
            const int r = m0 + wm * 32 + mi * 16 + quad + h * 8;
            if (MODE == 0 || MODE == 3) {
                float* crow = Cf + bz * sC + (size_t)r * Nc + n0 + wn * 64 + tq * 2;
                #pragma unroll
                for (int nf = 0; nf < 8; nf++) {
                    float2 v;
                    v.x = acc[mi][nf][h * 2 + 0] * alpha;
                    v.y = acc[mi][nf][h * 2 + 1] * alpha;
                    *(float2*)(crow + nf * 8) = v;
                }
            } else if (MODE == 4 || (MODE == 5 && which < 2)) {
                fp16* hrow = outCh + bz * sC + (size_t)r * Nc + n0 + wn * 64 + tq * 2;
                #pragma unroll
                for (int nf = 0; nf < 8; nf++) {
                    *(__half2*)(hrow + nf * 8) =
                        __halves2half2(__float2half_rn(acc[mi][nf][h * 2 + 0]),
                                       __float2half_rn(acc[mi][nf][h * 2 + 1]));
                }
            } else {  // MODE 5, V: transposed Vt[b][c][t]
                const int b = r >> 11, t = r & (TT - 1);
                const size_t base = (size_t)b * CC * TT + t;
                #pragma unroll
                for (int nf = 0; nf < 8; nf++) {
                    const int c = n0 + wn * 64 + nf * 8 + tq * 2;
                    outCh[base + (size_t)c * TT]       = __float2half_rn(acc[mi][nf][h * 2 + 0]);
                    outCh[base + (size_t)(c + 1) * TT] = __float2half_rn(acc[mi][nf][h * 2 + 1]);
                }
            }
        }
    }
}

// ---------------- fp32 -> fp16 convert ----------------
__global__ __launch_bounds__(256)
void conv_f16(const float* __restrict__ x, fp16* __restrict__ h, int n)
{
    int i = (blockIdx.x * 256 + threadIdx.x) * 4;
    if (i >= n) return;
    float4 v = *(const float4*)(x + i);
    __align__(8) fp16 hh[4];
    hh[0] = __float2half_rn(v.x); hh[1] = __float2half_rn(v.y);
    hh[2] = __float2half_rn(v.z); hh[3] = __float2half_rn(v.w);
    *(uint2*)(h + i) = *(uint2*)hh;
}

// 4 weight matrices: W[k][n] -> Wt fp16 [n][k], z selects matrix
__global__ __launch_bounds__(256)
void wconvT4(const float* __restrict__ w0, const float* __restrict__ w1,
             const float* __restrict__ w2, const float* __restrict__ w3,
             fp16* __restrict__ h0, fp16* __restrict__ h1,
             fp16* __restrict__ h2, fp16* __restrict__ h3)
{
    const int z = blockIdx.z;
    const float* W = (z == 0) ? w0 : (z == 1) ? w1 : (z == 2) ? w2 : w3;
    fp16* Th = (z == 0) ? h0 : (z == 1) ? h1 : (z == 2) ? h2 : h3;

    __shared__ float t[32][33];
    const int n0 = blockIdx.x * 32, k0 = blockIdx.y * 32;
    const int tx = threadIdx.x & 31, ty = threadIdx.x >> 5;
    #pragma unroll
    for (int i = 0; i < 4; i++)
        t[ty + 8*i][tx] = W[(size_t)(k0 + ty + 8*i) * CC + n0 + tx];
    __syncthreads();
    #pragma unroll
    for (int i = 0; i < 4; i++)
        Th[(size_t)(n0 + ty + 8*i) * CC + k0 + tx] = __float2half_rn(t[tx][ty + 8*i]);
}

// ---------------- causal softmax: fp32 row -> fp16 probs ----------------
__global__ __launch_bounds__(256)
void softmax_causal(const float* __restrict__ S, fp16* __restrict__ Ph)
{
    const int r = blockIdx.x;
    const int t = r & (TT - 1);
    const float* row = S + (size_t)r * TT;
    fp16* ph = Ph + (size_t)r * TT;
    const int len = t + 1;
    const int zmax = ((t >> 7) + 1) << 7;

    const int tid = threadIdx.x, lane = tid & 31, wid = tid >> 5;
    __shared__ float red[32];

    float v[8];
    float m = -3.0e38f;
    #pragma unroll
    for (int i = 0; i < 8; i++) {
        int s = tid + i * 256;
        v[i] = (s < len) ? row[s] : -3.0e38f;
        m = fmaxf(m, v[i]);
    }
    #pragma unroll
    for (int o = 16; o > 0; o >>= 1) m = fmaxf(m, __shfl_xor_sync(0xffffffffu, m, o));
    if (lane == 0) red[wid] = m;
    __syncthreads();
    if (tid < 32) {
        float x = (tid < 8) ? red[tid] : -3.0e38f;
        #pragma unroll
        for (int o = 4; o > 0; o >>= 1) x = fmaxf(x, __shfl_xor_sync(0xffffffffu, x, o));
        if (tid == 0) red[0] = x;
    }
    __syncthreads();
    m = red[0];
    __syncthreads();

    float sum = 0.0f;
    #pragma unroll
    for (int i = 0; i < 8; i++) {
        int s = tid + i * 256;
        if (s < len) { v[i] = expf(v[i] - m); sum += v[i]; }
    }
    #pragma unroll
    for (int o = 16; o > 0; o >>= 1) sum += __shfl_xor_sync(0xffffffffu, sum, o);
    if (lane == 0) red[wid] = sum;
    __syncthreads();
    if (tid < 32) {
        float x = (tid < 8) ? red[tid] : 0.0f;
        #pragma unroll
        for (int o = 4; o > 0; o >>= 1) x += __shfl_xor_sync(0xffffffffu, x, o);
        if (tid == 0) red[0] = x;
    }
    __syncthreads();
    const float inv = 1.0f / red[0];

    const fp16 z = __float2half_rn(0.0f);
    #pragma unroll
    for (int i = 0; i < 8; i++) {
        int s = tid + i * 256;
        if (s < len)       ph[s] = __float2half_rn(v[i] * inv);
        else if (s < zmax) ph[s] = z;
    }
}

// ---------------- launch ----------------
extern "C" void kernel_launch(void* const* d_in, const int* in_sizes, int n_in,
                              void* d_out, int out_size)
{
    const float* X  = (const float*)d_in[0];
    const float* Wq = (const float*)d_in[1];
    const float* Wk = (const float*)d_in[2];
    const float* Wv = (const float*)d_in[3];
    const float* Wo = (const float*)d_in[4];
    float* out = (float*)d_out;

    fp16 *Xh,*Wqh,*Wkh,*Wvh,*Woh;
    fp16 *Qh,*Kh,*Vth,*Ph,*Oh;
    float* S;
    cudaGetSymbolAddress((void**)&Xh, g_Xh);
    cudaGetSymbolAddress((void**)&Wqh, g_Wqh); cudaGetSymbolAddress((void**)&Wkh, g_Wkh);
    cudaGetSymbolAddress((void**)&Wvh, g_Wvh); cudaGetSymbolAddress((void**)&Woh, g_Woh);
    cudaGetSymbolAddress((void**)&Qh, g_Qh);   cudaGetSymbolAddress((void**)&Kh, g_Kh);
    cudaGetSymbolAddress((void**)&Vth, g_Vth);
    cudaGetSymbolAddress((void**)&Ph, g_Ph);   cudaGetSymbolAddress((void**)&Oh, g_Oh);
    cudaGetSymbolAddress((void**)&S, g_S);

    cudaFuncSetAttribute(gemm_mma<0>, cudaFuncAttributeMaxDynamicSharedMemorySize, SMEM_DYN);
    cudaFuncSetAttribute(gemm_mma<3>, cudaFuncAttributeMaxDynamicSharedMemorySize, SMEM_DYN);
    cudaFuncSetAttribute(gemm_mma<4>, cudaFuncAttributeMaxDynamicSharedMemorySize, SMEM_DYN);
    cudaFuncSetAttribute(gemm_mma<5>, cudaFuncAttributeMaxDynamicSharedMemorySize, SMEM_DYN);

    // 1) input convert
    conv_f16<<<MT*CC/1024, 256>>>(X, Xh, MT*CC);
    // 2) weight transposes (fp16)
    wconvT4<<<dim3(32,32,4), 256>>>(Wq, Wk, Wv, Wo, Wqh, Wkh, Wvh, Woh);

    // 3) fused QKV (bx: 0-7 Q, 8-15 K, 16-23 V-transposed)
    gemm_mma<5><<<dim3(24,64,1), 256, SMEM_DYN>>>(Xh, Wqh, nullptr, Qh,
                                                  Wkh, Wvh, Kh, Vth,
                                                  CC, CC, CC, CC, 0, 0, 0, 1.0f);

    // 4) scores (causal tile-skip): S = (Q @ K^T)/32
    gemm_mma<3><<<dim3(16,16,4), 256, SMEM_DYN>>>(Qh, Kh, S, nullptr,
                                                  nullptr, nullptr, nullptr, nullptr,
                                                  CC, CC, CC, TT,
                                                  (size_t)TT*CC, (size_t)TT*CC, (size_t)TT*TT,
                                                  1.0f/32.0f);

    // 5) softmax -> P fp16
    softmax_causal<<<BB*TT, 256>>>(S, Ph);

    // 6) O = P @ Vt^T (k-limited, heavy-first)
    gemm_mma<4><<<dim3(8,16,4), 256, SMEM_DYN>>>(Ph, Vth, nullptr, Oh,
                                                 nullptr, nullptr, nullptr, nullptr,
                                                 TT, TT, TT, CC,
                                                 (size_t)TT*TT, (size_t)CC*TT, (size_t)TT*CC,
                                                 1.0f);

    // 7) out = O @ Wo^T
    gemm_mma<0><<<dim3(8,64,1), 256, SMEM_DYN>>>(Oh, Woh, out, nullptr,
                                                 nullptr, nullptr, nullptr, nullptr,
                                                 CC, CC, CC, CC, 0, 0, 0, 1.0f);
}